// round 12
// baseline (speedup 1.0000x reference)
#include <cuda_runtime.h>
#include <math.h>

#define NB 64
#define NA 8732
#define NA4 2183            // NA/4 exact
#define NA4P 2560
#define NG 50
#define NC 21
#define NBX 18              // k_match blocks per batch
#define NSB 8               // k_select sub-blocks per batch
#define NAS4 273            // ceil(NA4/NSB)
#define CAP 4096
#define IOU_THR 0.5f
#define VXY 0.1f
#define VWH 0.2f
#define EPS16 9.765625e-4

// ---------------- device scratch ----------------
__device__ float    g_lossneg[NB * NA];
__device__ unsigned g_hcnt[NB * 2048];
__device__ float    g_hsum[NB * 2048];
__device__ unsigned g_cand[NB * CAP];
__device__ unsigned g_ccnt[NB];
__device__ int      g_tkt[NB];
__device__ float    g_psl1[NB * NBX];
__device__ float    g_pce [NB * NBX];
__device__ int      g_pnp [NB * NBX];
__device__ double   g_ob_cp[NB];
__device__ double   g_ob_cn[NB];
__device__ double   g_ob_np[NB];
__device__ double   g_ob_sl[NB];
__device__ int      g_ctr;

// ---------------- helpers ----------------
__device__ __forceinline__ double warpRedD(double v) {
    #pragma unroll
    for (int o = 16; o > 0; o >>= 1) v += __shfl_down_sync(0xFFFFFFFFu, v, o);
    return v;
}
__device__ __forceinline__ float warpRedF(float v) {
    #pragma unroll
    for (int o = 16; o > 0; o >>= 1) v += __shfl_down_sync(0xFFFFFFFFu, v, o);
    return v;
}
__device__ __forceinline__ int warpRedI(int v) {
    #pragma unroll
    for (int o = 16; o > 0; o >>= 1) v += __shfl_down_sync(0xFFFFFFFFu, v, o);
    return v;
}
__device__ __forceinline__ float smoothL1(float d) {
    float ad = fabsf(d);
    return ad < 1.0f ? 0.5f * d * d : ad - 0.5f;
}
__device__ __forceinline__ unsigned ordkey(float f) {
    unsigned u = __float_as_uint(f);
    return u ^ ((u >> 31) ? 0xFFFFFFFFu : 0x80000000u);
}
__device__ __forceinline__ float ordval(unsigned k) {
    unsigned u = (k & 0x80000000u) ? (k ^ 0x80000000u) : ~k;
    return __uint_as_float(u);
}
__device__ __forceinline__ unsigned warpSufIncl(unsigned v, int lane) {
    #pragma unroll
    for (int d = 1; d < 32; d <<= 1) {
        unsigned t = __shfl_down_sync(0xFFFFFFFFu, v, d);
        if (lane + d < 32) v += t;
    }
    return v;
}
// warp-aggregated append into a GLOBAL buffer
__device__ __forceinline__ void ballotAppendG(bool take, unsigned u, unsigned* buf,
                                              unsigned* cnt, int lane) {
    unsigned mask = __ballot_sync(0xFFFFFFFFu, take);
    if (take) {
        int leader = __ffs(mask) - 1;
        unsigned base = 0;
        if (lane == leader) base = atomicAdd(cnt, (unsigned)__popc(mask));
        base = __shfl_sync(mask, base, leader);
        unsigned p = base + (unsigned)__popc(mask & ((1u << lane) - 1u));
        if (p < CAP) buf[p] = u;
    }
}

// select crossing bin; BPT bins/thread, 256 threads (8 warps). Ends synced.
template<int BPT>
__device__ __forceinline__ void selectB(const unsigned* h, unsigned K,
        unsigned* s_w, unsigned* s_w2, unsigned* s_bin, unsigned* s_rem,
        int tid, int lane, int wid) {
    unsigned c[BPT];
    c[BPT - 1] = h[BPT - 1];
    #pragma unroll
    for (int j = BPT - 2; j >= 0; j--) c[j] = h[j] + c[j + 1];
    unsigned v = warpSufIncl(c[0], lane);
    if (lane == 0) s_w[wid] = v;
    __syncthreads();
    if (tid < 32) {
        unsigned t = (tid < 8) ? s_w[tid] : 0u;
        s_w2[tid] = warpSufIncl(t, tid);
    }
    __syncthreads();
    unsigned wexcl = (wid < 7) ? s_w2[wid + 1] : 0u;
    unsigned above = (v - c[0]) + wexcl;
    #pragma unroll
    for (int j = 0; j < BPT; j++) {
        unsigned sufi = above + c[j];
        unsigned sufe = sufi - h[j];
        if (sufe < K && K <= sufi) { *s_bin = (unsigned)(BPT * tid + j); *s_rem = K - sufe; }
    }
    __syncthreads();
}

// ---------------- kernel 1: match + box loss + CE (unchanged from R11) ----------------
__global__ __launch_bounds__(256) void k_match(const float* __restrict__ preg,
                        const float* __restrict__ pcls,
                        const float* __restrict__ ancs,
                        const float* __restrict__ gbox,
                        const int*   __restrict__ glab) {
    const int b = blockIdx.y;
    const int tid = threadIdx.x;
    const int a0 = blockIdx.x * 512 + tid;
    const int a1 = a0 + 256;

    __shared__ float4 s_gb[NG];
    __shared__ float  s_ga[NG];
    __shared__ int    s_gl[NG];
    if (tid < NG) {
        float4 gb = reinterpret_cast<const float4*>(gbox)[b * NG + tid];
        int    gl = glab[b * NG + tid];
        float  ag = (gb.z - gb.x) * (gb.w - gb.y);
        if (gl <= 0) { gb = make_float4(0.f, 0.f, 0.f, 0.f); ag = 0.f; }
        s_gb[tid] = gb;
        s_ga[tid] = ag;
        s_gl[tid] = gl;
    }
    __syncthreads();

    float sl1_c = 0.f, ce_c = 0.f;
    int pos_c = 0;

    const bool v0 = (a0 < NA), v1 = (a1 < NA);

    float4 anc0 = make_float4(0.5f, 0.5f, 1.f, 1.f), anc1 = anc0;
    if (v0) anc0 = reinterpret_cast<const float4*>(ancs)[a0];
    if (v1) anc1 = reinterpret_cast<const float4*>(ancs)[a1];

    float al0 = anc0.x - anc0.z * 0.5f, at0 = anc0.y - anc0.w * 0.5f;
    float ar0 = anc0.x + anc0.z * 0.5f, ab0 = anc0.y + anc0.w * 0.5f;
    float area0 = (ar0 - al0) * (ab0 - at0);
    float al1 = anc1.x - anc1.z * 0.5f, at1 = anc1.y - anc1.w * 0.5f;
    float ar1 = anc1.x + anc1.z * 0.5f, ab1 = anc1.y + anc1.w * 0.5f;
    float area1 = (ar1 - al1) * (ab1 - at1);

    float inb0 = -1.f, unb0 = 1.f, inb1 = -1.f, unb1 = 1.f;
    int bi0 = 0, bi1 = 0;
    #pragma unroll
    for (int g = 0; g < NG; g++) {
        float4 gb = s_gb[g];
        float ga = s_ga[g];
        {
            float ltx = fmaxf(gb.x, al0), lty = fmaxf(gb.y, at0);
            float rbx = fminf(gb.z, ar0), rby = fminf(gb.w, ab0);
            float w = fmaxf(rbx - ltx, 0.0f), h = fmaxf(rby - lty, 0.0f);
            float inter = w * h;
            float uni = ga + area0 - inter;
            if (inter * unb0 > inb0 * uni) { inb0 = inter; unb0 = uni; bi0 = g; }
        }
        {
            float ltx = fmaxf(gb.x, al1), lty = fmaxf(gb.y, at1);
            float rbx = fminf(gb.z, ar1), rby = fminf(gb.w, ab1);
            float w = fmaxf(rbx - ltx, 0.0f), h = fmaxf(rby - lty, 0.0f);
            float inter = w * h;
            float uni = ga + area1 - inter;
            if (inter * unb1 > inb1 * uni) { inb1 = inter; unb1 = uni; bi1 = g; }
        }
    }
    bool pos0 = (2.0f * inb0 >= unb0);
    bool pos1 = (2.0f * inb1 >= unb1);

    const float* pregb = preg + (size_t)b * 4 * NA;
    const float* pclsb = pcls + (size_t)b * NC * NA;
    unsigned* hcntb = &g_hcnt[b * 2048];
    float*    hsumb = &g_hsum[b * 2048];

    if (v0) {
        float4 gb = s_gb[bi0];
        float gcx = (gb.x + gb.z) * 0.5f, gcy = (gb.y + gb.w) * 0.5f;
        float gw = gb.z - gb.x, gh = gb.w - gb.y;
        float tx = (gcx - anc0.x) / (anc0.z * VXY);
        float ty = (gcy - anc0.y) / (anc0.w * VXY);
        float tw = __logf(fmaxf(gw, 1e-6f) / anc0.z) * (1.0f / VWH);
        float th = __logf(fmaxf(gh, 1e-6f) / anc0.w) * (1.0f / VWH);
        float d0 = pregb[0 * NA + a0] - tx;
        float d1 = pregb[1 * NA + a0] - ty;
        float d2 = pregb[2 * NA + a0] - tw;
        float d3 = pregb[3 * NA + a0] - th;
        float sl1 = smoothL1(d0) + smoothL1(d1) + smoothL1(d2) + smoothL1(d3);

        const float* pc = pclsb + a0;
        float s = 0.0f;
        #pragma unroll
        for (int c = 0; c < NC; c++) s += __expf(pc[c * NA]);
        float lse = __logf(s);
        int lab = pos0 ? s_gl[bi0] : 0;
        float ce = lse - pc[lab * NA];

        g_lossneg[b * NA + a0] = pos0 ? -1.0f : ce;
        if (pos0) { pos_c++; ce_c += ce; sl1_c += sl1; }
        else {
            unsigned kk = ordkey(ce) >> 21;
            atomicAdd(&hcntb[kk], 1u);
            atomicAdd(&hsumb[kk], ce);
        }
    }
    if (v1) {
        float4 gb = s_gb[bi1];
        float gcx = (gb.x + gb.z) * 0.5f, gcy = (gb.y + gb.w) * 0.5f;
        float gw = gb.z - gb.x, gh = gb.w - gb.y;
        float tx = (gcx - anc1.x) / (anc1.z * VXY);
        float ty = (gcy - anc1.y) / (anc1.w * VXY);
        float tw = __logf(fmaxf(gw, 1e-6f) / anc1.z) * (1.0f / VWH);
        float th = __logf(fmaxf(gh, 1e-6f) / anc1.w) * (1.0f / VWH);
        float d0 = pregb[0 * NA + a1] - tx;
        float d1 = pregb[1 * NA + a1] - ty;
        float d2 = pregb[2 * NA + a1] - tw;
        float d3 = pregb[3 * NA + a1] - th;
        float sl1 = smoothL1(d0) + smoothL1(d1) + smoothL1(d2) + smoothL1(d3);

        const float* pc = pclsb + a1;
        float s = 0.0f;
        #pragma unroll
        for (int c = 0; c < NC; c++) s += __expf(pc[c * NA]);
        float lse = __logf(s);
        int lab = pos1 ? s_gl[bi1] : 0;
        float ce = lse - pc[lab * NA];

        g_lossneg[b * NA + a1] = pos1 ? -1.0f : ce;
        if (pos1) { pos_c++; ce_c += ce; sl1_c += sl1; }
        else {
            unsigned kk = ordkey(ce) >> 21;
            atomicAdd(&hcntb[kk], 1u);
            atomicAdd(&hsumb[kk], ce);
        }
    }

    sl1_c = warpRedF(sl1_c);
    ce_c  = warpRedF(ce_c);
    float posf = warpRedF((float)pos_c);
    __shared__ float sh0[8], sh1[8], sh2[8];
    int wid = tid >> 5, lid = tid & 31;
    if (lid == 0) { sh0[wid] = sl1_c; sh1[wid] = ce_c; sh2[wid] = posf; }
    __syncthreads();
    if (wid == 0) {
        float x0 = (lid < 8) ? sh0[lid] : 0.f;
        float x1 = (lid < 8) ? sh1[lid] : 0.f;
        float x2 = (lid < 8) ? sh2[lid] : 0.f;
        x0 = warpRedF(x0); x1 = warpRedF(x1); x2 = warpRedF(x2);
        if (lid == 0) {
            int p = b * NBX + blockIdx.x;
            g_psl1[p] = x0;
            g_pce [p] = x1;
            g_pnp [p] = (int)(x2 + 0.5f);
        }
    }
}

// ---------------- kernel 2: distributed compaction + candidate-only select ----------------
__global__ __launch_bounds__(256) void k_select(float* __restrict__ out) {
    const int b = blockIdx.y;
    const int sub = blockIdx.x;
    const int tid = threadIdx.x;
    const int lane = tid & 31;
    const int wid = tid >> 5;

    __shared__ unsigned s_h2[2048];
    __shared__ unsigned s_cnt3[1024];
    __shared__ unsigned s_w[8], s_w2[32];
    __shared__ unsigned s_bin, s_rem, s_m1;
    __shared__ int s_npos, s_ticket;
    __shared__ double s_ce, s_sl;
    __shared__ double sd[8];

    // K (all blocks need it)
    if (wid == 0) {
        int np = (lane < NBX) ? g_pnp[b * NBX + lane] : 0;
        np = warpRedI(np);
        if (lane == 0) s_npos = np;
    }
    __syncthreads();
    int npos = s_npos;
    int numneg = NA - npos;
    int K = (npos > 0) ? min(3 * npos, numneg) : (numneg > 0 ? 1 : 0);

    // load level-1 histogram, 8 bins/thread (counts; sums kept for last block)
    unsigned hc[8]; float hsv[8];
    {
        const uint4*  gc4 = reinterpret_cast<const uint4*>(&g_hcnt[b * 2048]);
        const float4* gs4 = reinterpret_cast<const float4*>(&g_hsum[b * 2048]);
        uint4  c0 = gc4[2 * tid], c1 = gc4[2 * tid + 1];
        float4 s0 = gs4[2 * tid], s1 = gs4[2 * tid + 1];
        hc[0] = c0.x; hc[1] = c0.y; hc[2] = c0.z; hc[3] = c0.w;
        hc[4] = c1.x; hc[5] = c1.y; hc[6] = c1.z; hc[7] = c1.w;
        hsv[0] = s0.x; hsv[1] = s0.y; hsv[2] = s0.z; hsv[3] = s0.w;
        hsv[4] = s1.x; hsv[5] = s1.y; hsv[6] = s1.z; hsv[7] = s1.w;
    }

    unsigned B1 = 0, rem1 = 0, M1 = 0;
    if (K > 0) {
        selectB<8>(hc, (unsigned)K, s_w, s_w2, &s_bin, &s_rem, tid, lane, wid);
        B1 = s_bin; rem1 = s_rem;
        if ((B1 >> 3) == (unsigned)tid) s_m1 = hc[B1 & 7];
        __syncthreads();
        M1 = s_m1;

        // distributed compaction of bin-B1 members into global candidate buffer
        if (M1 <= CAP) {
            const float4* base4 = reinterpret_cast<const float4*>(&g_lossneg[b * NA]);
            unsigned* candb = &g_cand[b * CAP];
            int i0 = sub * NAS4;
            int i1 = min(NA4, i0 + NAS4);
            // pad so every lane participates in ballots
            int span = ((i1 - i0 + 255) & ~255);
            for (int t = tid; t < span; t += 256) {
                int i = i0 + t;
                bool vld = (i < i1);
                float4 f = make_float4(0.f, 0.f, 0.f, 0.f);
                if (vld) f = base4[i];
                unsigned k0 = ordkey(f.x), k1 = ordkey(f.y), k2 = ordkey(f.z), k3 = ordkey(f.w);
                ballotAppendG(vld && (k0 >> 21) == B1, k0, candb, &g_ccnt[b], lane);
                ballotAppendG(vld && (k1 >> 21) == B1, k1, candb, &g_ccnt[b], lane);
                ballotAppendG(vld && (k2 >> 21) == B1, k2, candb, &g_ccnt[b], lane);
                ballotAppendG(vld && (k3 >> 21) == B1, k3, candb, &g_ccnt[b], lane);
            }
        }
    }

    // per-batch ticket; only last sub-block continues
    if (tid == 0) {
        __threadfence();
        s_ticket = atomicAdd(&g_tkt[b], 1);
    }
    __syncthreads();
    if (s_ticket != NSB - 1) return;

    // ---- last sub-block of batch b ----
    if (tid == 0) { g_tkt[b] = 0; g_ccnt[b] = 0; }

    // rezero level-1 histograms for next replay
    {
        uint4*  gc4 = reinterpret_cast<uint4*>(&g_hcnt[b * 2048]);
        float4* gs4 = reinterpret_cast<float4*>(&g_hsum[b * 2048]);
        gc4[2 * tid] = make_uint4(0, 0, 0, 0);
        gc4[2 * tid + 1] = make_uint4(0, 0, 0, 0);
        gs4[2 * tid] = make_float4(0.f, 0.f, 0.f, 0.f);
        gs4[2 * tid + 1] = make_float4(0.f, 0.f, 0.f, 0.f);
    }

    // ce / sl1 partial reduction
    if (wid == 1) {
        double ce = 0.0, sl = 0.0;
        if (lane < NBX) {
            int p = b * NBX + lane;
            ce = (double)g_pce[p];
            sl = (double)g_psl1[p];
        }
        ce = warpRedD(ce); sl = warpRedD(sl);
        if (lane == 0) { s_ce = ce; s_sl = sl; }
    }

    // zero smem histograms
    s_h2[tid] = 0; s_h2[tid + 256] = 0; s_h2[tid + 512] = 0; s_h2[tid + 768] = 0;
    s_h2[tid + 1024] = 0; s_h2[tid + 1280] = 0; s_h2[tid + 1536] = 0; s_h2[tid + 1792] = 0;
    s_cnt3[tid] = 0; s_cnt3[tid + 256] = 0; s_cnt3[tid + 512] = 0; s_cnt3[tid + 768] = 0;
    __syncthreads();

    double dsum = 0.0;
    double negsum = 0.0;

    if (K > 0) {
        // exact above-B1 sum from precomputed value sums (registers)
        #pragma unroll
        for (int j = 0; j < 8; j++)
            if ((unsigned)(8 * tid + j) > B1) dsum += (double)hsv[j];

        bool compact = (M1 <= CAP);
        const unsigned* candb = &g_cand[b * CAP];
        const float4* base4 = reinterpret_cast<const float4*>(&g_lossneg[b * NA]);

        // level-2 histogram
        if (compact) {
            for (int i = tid; i < (int)M1; i += 256)
                atomicAdd(&s_h2[(candb[i] >> 10) & 2047u], 1u);
        } else {
            for (int i = tid; i < NA4; i += 256) {
                float4 f = base4[i];
                unsigned kk[4] = { ordkey(f.x), ordkey(f.y), ordkey(f.z), ordkey(f.w) };
                #pragma unroll
                for (int j = 0; j < 4; j++)
                    if ((kk[j] >> 21) == B1) atomicAdd(&s_h2[(kk[j] >> 10) & 2047u], 1u);
            }
        }
        __syncthreads();

        unsigned h2l[8];
        #pragma unroll
        for (int j = 0; j < 8; j++) h2l[j] = s_h2[8 * tid + j];
        selectB<8>(h2l, rem1, s_w, s_w2, &s_bin, &s_rem, tid, lane, wid);
        unsigned B2 = s_bin, rem2 = s_rem;
        __syncthreads();

        // level-3 exact-key counts + above-B2 sum
        if (compact) {
            for (int i = tid; i < (int)M1; i += 256) {
                unsigned k = candb[i];
                unsigned sb = (k >> 10) & 2047u;
                if (sb > B2) dsum += (double)ordval(k);
                else if (sb == B2) atomicAdd(&s_cnt3[k & 1023u], 1u);
            }
        } else {
            for (int i = tid; i < NA4; i += 256) {
                float4 f = base4[i];
                unsigned kk[4] = { ordkey(f.x), ordkey(f.y), ordkey(f.z), ordkey(f.w) };
                #pragma unroll
                for (int j = 0; j < 4; j++) {
                    unsigned k = kk[j];
                    if ((k >> 21) == B1) {
                        unsigned sb = (k >> 10) & 2047u;
                        if (sb > B2) dsum += (double)ordval(k);
                        else if (sb == B2) atomicAdd(&s_cnt3[k & 1023u], 1u);
                    }
                }
            }
        }
        __syncthreads();

        unsigned h3l[4];
        #pragma unroll
        for (int j = 0; j < 4; j++) h3l[j] = s_cnt3[4 * tid + j];
        selectB<4>(h3l, rem2, s_w, s_w2, &s_bin, &s_rem, tid, lane, wid);
        unsigned B3 = s_bin, rem3 = s_rem;

        unsigned pref = (B1 << 21) | (B2 << 10);
        for (int j = tid; j < 1024; j += 256) {
            unsigned c = s_cnt3[j];
            if ((unsigned)j > B3 && c)
                dsum += (double)c * (double)ordval(pref | (unsigned)j);
        }
        float pv = ordval(pref | B3);

        double s = warpRedD(dsum);
        if (lane == 0) sd[wid] = s;
        __syncthreads();
        if (wid == 0) {
            double t = (lane < 8) ? sd[lane] : 0.0;
            t = warpRedD(t);
            if (lane == 0) sd[0] = t + (double)rem3 * (double)pv;
        }
        __syncthreads();
        negsum = sd[0];
    } else {
        __syncthreads();
    }

    // publish per-batch results; global last block combines
    if (tid == 0) {
        double np = (double)npos;
        double nums = fmax(np, (double)EPS16);
        g_ob_cp[b] = s_ce / nums;
        g_ob_cn[b] = negsum / nums;
        g_ob_np[b] = np;
        g_ob_sl[b] = s_sl;
        __threadfence();
        s_ticket = atomicAdd(&g_ctr, 1);
    }
    __syncthreads();

    if (s_ticket == NB - 1) {
        double cp = 0.0, cn = 0.0, np = 0.0, sl = 0.0;
        if (tid < NB) {
            cp = g_ob_cp[tid]; cn = g_ob_cn[tid];
            np = g_ob_np[tid]; sl = g_ob_sl[tid];
        }
        cp = warpRedD(cp); cn = warpRedD(cn); np = warpRedD(np); sl = warpRedD(sl);
        __shared__ double f0[2], f1[2], f2[2], f3[2];
        if (lane == 0 && tid < NB) {
            f0[wid] = cp; f1[wid] = cn; f2[wid] = np; f3[wid] = sl;
        }
        __syncthreads();
        if (tid == 0) {
            double CP = f0[0] + f0[1];
            double CN = f1[0] + f1[1];
            double NP = f2[0] + f2[1];
            double SL = f3[0] + f3[1];
            double lbox = SL / fmax(NP, 1.0);
            out[0] = (float)(lbox + CP / (double)NB + CN / (double)NB);
            g_ctr = 0;
        }
    }
}

// ---------------- launch ----------------
extern "C" void kernel_launch(void* const* d_in, const int* in_sizes, int n_in,
                              void* d_out, int out_size) {
    const float* preg = (const float*)d_in[0];
    const float* pcls = (const float*)d_in[1];
    const float* ancs = (const float*)d_in[2];
    const float* gbox = (const float*)d_in[3];
    const int*   glab = (const int*)d_in[4];
    float* out = (float*)d_out;

    dim3 gridm(NBX, NB);
    k_match<<<gridm, 256>>>(preg, pcls, ancs, gbox, glab);
    dim3 grids(NSB, NB);
    k_select<<<grids, 256>>>(out);
}

// round 13
// speedup vs baseline: 1.4126x; 1.4126x over previous
#include <cuda_runtime.h>
#include <math.h>

#define NB 64
#define NA 8732
#define NA4 2183            // NA/4 exact
#define NG 50
#define NC 21
#define NBX 18              // k_match blocks per batch
#define IOU_THR 0.5f
#define VXY 0.1f
#define VWH 0.2f
#define EPS16 9.765625e-4

// ---------------- device scratch ----------------
__device__ float    g_lossneg[NB * NA];
__device__ unsigned g_hcnt[NB * 2048];    // per-batch level-1 counts (negatives only)
__device__ float    g_hsum[NB * 2048];    // per-batch level-1 value sums
__device__ float    g_psl1[NB * NBX];
__device__ float    g_pce [NB * NBX];
__device__ int      g_pnp [NB * NBX];
__device__ double   g_ob_cp[NB];
__device__ double   g_ob_cn[NB];
__device__ double   g_ob_np[NB];
__device__ double   g_ob_sl[NB];
__device__ int      g_ctr;

// ---------------- helpers ----------------
__device__ __forceinline__ double warpRedD(double v) {
    #pragma unroll
    for (int o = 16; o > 0; o >>= 1) v += __shfl_down_sync(0xFFFFFFFFu, v, o);
    return v;
}
__device__ __forceinline__ float warpRedF(float v) {
    #pragma unroll
    for (int o = 16; o > 0; o >>= 1) v += __shfl_down_sync(0xFFFFFFFFu, v, o);
    return v;
}
__device__ __forceinline__ float smoothL1(float d) {
    float ad = fabsf(d);
    return ad < 1.0f ? 0.5f * d * d : ad - 0.5f;
}
__device__ __forceinline__ unsigned ordkey(float f) {
    unsigned u = __float_as_uint(f);
    return u ^ ((u >> 31) ? 0xFFFFFFFFu : 0x80000000u);
}
__device__ __forceinline__ float ordval(unsigned k) {
    unsigned u = (k & 0x80000000u) ? (k ^ 0x80000000u) : ~k;
    return __uint_as_float(u);
}
__device__ __forceinline__ unsigned warpSufIncl(unsigned v, int lane) {
    #pragma unroll
    for (int d = 1; d < 32; d <<= 1) {
        unsigned t = __shfl_down_sync(0xFFFFFFFFu, v, d);
        if (lane + d < 32) v += t;
    }
    return v;
}
__device__ __forceinline__ unsigned warpInclScan(unsigned v, int lane) {
    #pragma unroll
    for (int d = 1; d < 32; d <<= 1) {
        unsigned t = __shfl_up_sync(0xFFFFFFFFu, v, d);
        if (lane >= d) v += t;
    }
    return v;
}

// crossing-bin select over BPT*512 bins, 512 threads / 16 warps. Ends synced.
template<int BPT>
__device__ __forceinline__ void selectB(const unsigned* h, unsigned K,
        unsigned* s_w, unsigned* s_w2, unsigned* s_bin, unsigned* s_rem,
        int tid, int lane, int wid) {
    unsigned c[BPT];
    c[BPT - 1] = h[BPT - 1];
    #pragma unroll
    for (int j = BPT - 2; j >= 0; j--) c[j] = h[j] + c[j + 1];
    unsigned v = warpSufIncl(c[0], lane);
    if (lane == 0) s_w[wid] = v;
    __syncthreads();
    if (tid < 32) {
        unsigned t = (tid < 16) ? s_w[tid] : 0u;
        s_w2[tid] = warpSufIncl(t, tid);
    }
    __syncthreads();
    unsigned wexcl = (wid < 15) ? s_w2[wid + 1] : 0u;
    unsigned above = (v - c[0]) + wexcl;
    #pragma unroll
    for (int j = 0; j < BPT; j++) {
        unsigned sufi = above + c[j];
        unsigned sufe = sufi - h[j];
        if (sufe < K && K <= sufi) { *s_bin = (unsigned)(BPT * tid + j); *s_rem = K - sufe; }
    }
    __syncthreads();
}

// ---------------- kernel 1: match + box loss + CE (verbatim R11) ----------------
__global__ __launch_bounds__(256) void k_match(const float* __restrict__ preg,
                        const float* __restrict__ pcls,
                        const float* __restrict__ ancs,
                        const float* __restrict__ gbox,
                        const int*   __restrict__ glab) {
    const int b = blockIdx.y;
    const int tid = threadIdx.x;
    const int a0 = blockIdx.x * 512 + tid;
    const int a1 = a0 + 256;

    __shared__ float4 s_gb[NG];
    __shared__ float  s_ga[NG];
    __shared__ int    s_gl[NG];
    if (tid < NG) {
        float4 gb = reinterpret_cast<const float4*>(gbox)[b * NG + tid];
        int    gl = glab[b * NG + tid];
        float  ag = (gb.z - gb.x) * (gb.w - gb.y);
        if (gl <= 0) { gb = make_float4(0.f, 0.f, 0.f, 0.f); ag = 0.f; }
        s_gb[tid] = gb;
        s_ga[tid] = ag;
        s_gl[tid] = gl;
    }
    __syncthreads();

    float sl1_c = 0.f, ce_c = 0.f;
    int pos_c = 0;

    const bool v0 = (a0 < NA), v1 = (a1 < NA);

    float4 anc0 = make_float4(0.5f, 0.5f, 1.f, 1.f), anc1 = anc0;
    if (v0) anc0 = reinterpret_cast<const float4*>(ancs)[a0];
    if (v1) anc1 = reinterpret_cast<const float4*>(ancs)[a1];

    float al0 = anc0.x - anc0.z * 0.5f, at0 = anc0.y - anc0.w * 0.5f;
    float ar0 = anc0.x + anc0.z * 0.5f, ab0 = anc0.y + anc0.w * 0.5f;
    float area0 = (ar0 - al0) * (ab0 - at0);
    float al1 = anc1.x - anc1.z * 0.5f, at1 = anc1.y - anc1.w * 0.5f;
    float ar1 = anc1.x + anc1.z * 0.5f, ab1 = anc1.y + anc1.w * 0.5f;
    float area1 = (ar1 - al1) * (ab1 - at1);

    float inb0 = -1.f, unb0 = 1.f, inb1 = -1.f, unb1 = 1.f;
    int bi0 = 0, bi1 = 0;
    #pragma unroll
    for (int g = 0; g < NG; g++) {
        float4 gb = s_gb[g];
        float ga = s_ga[g];
        {
            float ltx = fmaxf(gb.x, al0), lty = fmaxf(gb.y, at0);
            float rbx = fminf(gb.z, ar0), rby = fminf(gb.w, ab0);
            float w = fmaxf(rbx - ltx, 0.0f), h = fmaxf(rby - lty, 0.0f);
            float inter = w * h;
            float uni = ga + area0 - inter;
            if (inter * unb0 > inb0 * uni) { inb0 = inter; unb0 = uni; bi0 = g; }
        }
        {
            float ltx = fmaxf(gb.x, al1), lty = fmaxf(gb.y, at1);
            float rbx = fminf(gb.z, ar1), rby = fminf(gb.w, ab1);
            float w = fmaxf(rbx - ltx, 0.0f), h = fmaxf(rby - lty, 0.0f);
            float inter = w * h;
            float uni = ga + area1 - inter;
            if (inter * unb1 > inb1 * uni) { inb1 = inter; unb1 = uni; bi1 = g; }
        }
    }
    bool pos0 = (2.0f * inb0 >= unb0);
    bool pos1 = (2.0f * inb1 >= unb1);

    const float* pregb = preg + (size_t)b * 4 * NA;
    const float* pclsb = pcls + (size_t)b * NC * NA;
    unsigned* hcntb = &g_hcnt[b * 2048];
    float*    hsumb = &g_hsum[b * 2048];

    if (v0) {
        float4 gb = s_gb[bi0];
        float gcx = (gb.x + gb.z) * 0.5f, gcy = (gb.y + gb.w) * 0.5f;
        float gw = gb.z - gb.x, gh = gb.w - gb.y;
        float tx = (gcx - anc0.x) / (anc0.z * VXY);
        float ty = (gcy - anc0.y) / (anc0.w * VXY);
        float tw = __logf(fmaxf(gw, 1e-6f) / anc0.z) * (1.0f / VWH);
        float th = __logf(fmaxf(gh, 1e-6f) / anc0.w) * (1.0f / VWH);
        float d0 = pregb[0 * NA + a0] - tx;
        float d1 = pregb[1 * NA + a0] - ty;
        float d2 = pregb[2 * NA + a0] - tw;
        float d3 = pregb[3 * NA + a0] - th;
        float sl1 = smoothL1(d0) + smoothL1(d1) + smoothL1(d2) + smoothL1(d3);

        const float* pc = pclsb + a0;
        float s = 0.0f;
        #pragma unroll
        for (int c = 0; c < NC; c++) s += __expf(pc[c * NA]);
        float lse = __logf(s);
        int lab = pos0 ? s_gl[bi0] : 0;
        float ce = lse - pc[lab * NA];

        g_lossneg[b * NA + a0] = pos0 ? -1.0f : ce;
        if (pos0) { pos_c++; ce_c += ce; sl1_c += sl1; }
        else {
            unsigned kk = ordkey(ce) >> 21;
            atomicAdd(&hcntb[kk], 1u);
            atomicAdd(&hsumb[kk], ce);
        }
    }
    if (v1) {
        float4 gb = s_gb[bi1];
        float gcx = (gb.x + gb.z) * 0.5f, gcy = (gb.y + gb.w) * 0.5f;
        float gw = gb.z - gb.x, gh = gb.w - gb.y;
        float tx = (gcx - anc1.x) / (anc1.z * VXY);
        float ty = (gcy - anc1.y) / (anc1.w * VXY);
        float tw = __logf(fmaxf(gw, 1e-6f) / anc1.z) * (1.0f / VWH);
        float th = __logf(fmaxf(gh, 1e-6f) / anc1.w) * (1.0f / VWH);
        float d0 = pregb[0 * NA + a1] - tx;
        float d1 = pregb[1 * NA + a1] - ty;
        float d2 = pregb[2 * NA + a1] - tw;
        float d3 = pregb[3 * NA + a1] - th;
        float sl1 = smoothL1(d0) + smoothL1(d1) + smoothL1(d2) + smoothL1(d3);

        const float* pc = pclsb + a1;
        float s = 0.0f;
        #pragma unroll
        for (int c = 0; c < NC; c++) s += __expf(pc[c * NA]);
        float lse = __logf(s);
        int lab = pos1 ? s_gl[bi1] : 0;
        float ce = lse - pc[lab * NA];

        g_lossneg[b * NA + a1] = pos1 ? -1.0f : ce;
        if (pos1) { pos_c++; ce_c += ce; sl1_c += sl1; }
        else {
            unsigned kk = ordkey(ce) >> 21;
            atomicAdd(&hcntb[kk], 1u);
            atomicAdd(&hsumb[kk], ce);
        }
    }

    sl1_c = warpRedF(sl1_c);
    ce_c  = warpRedF(ce_c);
    float posf = warpRedF((float)pos_c);
    __shared__ float sh0[8], sh1[8], sh2[8];
    int wid = tid >> 5, lid = tid & 31;
    if (lid == 0) { sh0[wid] = sl1_c; sh1[wid] = ce_c; sh2[wid] = posf; }
    __syncthreads();
    if (wid == 0) {
        float x0 = (lid < 8) ? sh0[lid] : 0.f;
        float x1 = (lid < 8) ? sh1[lid] : 0.f;
        float x2 = (lid < 8) ? sh2[lid] : 0.f;
        x0 = warpRedF(x0); x1 = warpRedF(x1); x2 = warpRedF(x2);
        if (lid == 0) {
            int p = b * NBX + blockIdx.x;
            g_psl1[p] = x0;
            g_pce [p] = x1;
            g_pnp [p] = (int)(x2 + 0.5f);
        }
    }
}

// ---------------- kernel 2: register-batched, convergence-free select ----------------
__global__ __launch_bounds__(512) void k_select(float* __restrict__ out) {
    const int b = blockIdx.x;
    const int tid = threadIdx.x;
    const int lane = tid & 31;
    const int wid = tid >> 5;

    __shared__ unsigned s_cand[NA + 4];   // all bin-B1 members fit, no fallback
    __shared__ unsigned s_h2[2048];       // level-2 hist; first 1024 reused as cnt3
    __shared__ unsigned s_w[16], s_w2[32];
    __shared__ unsigned s_bin, s_rem, s_m1;
    __shared__ double s_np, s_ce, s_sl;
    __shared__ int s_ticket;
    __shared__ double sd[16];

    // ---- batched register load of this batch's lossneg (no convergent ops between) ----
    const float4* base4 = reinterpret_cast<const float4*>(&g_lossneg[b * NA]);
    float4 v0 = base4[tid];
    float4 v1 = base4[tid + 512];
    float4 v2 = base4[tid + 1024];
    float4 v3 = base4[tid + 1536];
    float4 v4 = make_float4(-1.f, -1.f, -1.f, -1.f);        // sentinel: never selected
    if (tid < NA4 - 2048) v4 = base4[tid + 2048];

    // level-1 histogram: counts + sums, 4 bins/thread; rezero for next replay
    uint4*  gc4 = reinterpret_cast<uint4*>(&g_hcnt[b * 2048]);
    float4* gs4 = reinterpret_cast<float4*>(&g_hsum[b * 2048]);
    uint4  hc = gc4[tid];
    float4 hs = gs4[tid];
    gc4[tid] = make_uint4(0, 0, 0, 0);
    gs4[tid] = make_float4(0.f, 0.f, 0.f, 0.f);

    // zero level-2 histogram
    s_h2[tid] = 0; s_h2[tid + 512] = 0; s_h2[tid + 1024] = 0; s_h2[tid + 1536] = 0;

    if (wid == 15) {
        double np = 0.0, ce = 0.0, sl = 0.0;
        if (lane < NBX) {
            int p = b * NBX + lane;
            np = (double)g_pnp[p];
            ce = (double)g_pce[p];
            sl = (double)g_psl1[p];
        }
        np = warpRedD(np); ce = warpRedD(ce); sl = warpRedD(sl);
        if (lane == 0) { s_np = np; s_ce = ce; s_sl = sl; }
    }
    __syncthreads();

    int npos = (int)(s_np + 0.5);
    int numneg = NA - npos;
    int K = (npos > 0) ? min(3 * npos, numneg) : (numneg > 0 ? 1 : 0);

    // my 20 keys in registers
    unsigned k[20];
    k[0]=ordkey(v0.x); k[1]=ordkey(v0.y); k[2]=ordkey(v0.z); k[3]=ordkey(v0.w);
    k[4]=ordkey(v1.x); k[5]=ordkey(v1.y); k[6]=ordkey(v1.z); k[7]=ordkey(v1.w);
    k[8]=ordkey(v2.x); k[9]=ordkey(v2.y); k[10]=ordkey(v2.z); k[11]=ordkey(v2.w);
    k[12]=ordkey(v3.x); k[13]=ordkey(v3.y); k[14]=ordkey(v3.z); k[15]=ordkey(v3.w);
    k[16]=ordkey(v4.x); k[17]=ordkey(v4.y); k[18]=ordkey(v4.z); k[19]=ordkey(v4.w);

    double dsumA = 0.0, dsumB = 0.0;
    double negsum = 0.0;

    if (K > 0) {
        // ---- level 1: B1 from counts; exact above-B1 sum from value sums ----
        unsigned hcl[4] = { hc.x, hc.y, hc.z, hc.w };
        selectB<4>(hcl, (unsigned)K, s_w, s_w2, &s_bin, &s_rem, tid, lane, wid);
        unsigned B1 = s_bin, rem1 = s_rem;
        if ((B1 >> 2) == (unsigned)tid) s_m1 = hcl[B1 & 3];
        {
            unsigned base = 4u * tid;
            if (base + 0 > B1) dsumA += (double)hs.x;
            if (base + 1 > B1) dsumB += (double)hs.y;
            if (base + 2 > B1) dsumA += (double)hs.z;
            if (base + 3 > B1) dsumB += (double)hs.w;
        }
        __syncthreads();
        unsigned M1 = s_m1;

        // ---- compaction: count (pure ALU) -> block exclusive scan -> STS writes ----
        unsigned cnt = 0;
        #pragma unroll
        for (int j = 0; j < 20; j++) cnt += ((k[j] >> 21) == B1);

        unsigned incl = warpInclScan(cnt, lane);
        if (lane == 31) s_w[wid] = incl;
        __syncthreads();
        if (tid < 32) {
            unsigned t = (tid < 16) ? s_w[tid] : 0u;
            unsigned ic = warpInclScan(t, tid);
            s_w2[tid] = ic - t;      // exclusive warp-total prefix
        }
        __syncthreads();
        unsigned off = (incl - cnt) + s_w2[wid];
        #pragma unroll
        for (int j = 0; j < 20; j++)
            if ((k[j] >> 21) == B1) s_cand[off++] = k[j];
        __syncthreads();

        // ---- level 2 histogram over candidates (mantissa-spread bins) ----
        for (int i = tid; i < (int)M1; i += 512)
            atomicAdd(&s_h2[(s_cand[i] >> 10) & 2047u], 1u);
        __syncthreads();

        unsigned h2l[4] = { s_h2[4 * tid], s_h2[4 * tid + 1], s_h2[4 * tid + 2], s_h2[4 * tid + 3] };
        selectB<4>(h2l, rem1, s_w, s_w2, &s_bin, &s_rem, tid, lane, wid);
        unsigned B2 = s_bin, rem2 = s_rem;

        // reuse s_h2[0..1023] as exact-key cnt3
        s_h2[tid] = 0; s_h2[tid + 512] = 0;
        __syncthreads();

        // ---- level 3: above-B2 sum + exact-key counts ----
        for (int i = tid; i < (int)M1; i += 512) {
            unsigned kk = s_cand[i];
            unsigned sb = (kk >> 10) & 2047u;
            if (sb > B2) dsumA += (double)ordval(kk);
            else if (sb == B2) atomicAdd(&s_h2[kk & 1023u], 1u);
        }
        __syncthreads();

        unsigned h3l[2] = { s_h2[2 * tid], s_h2[2 * tid + 1] };
        selectB<2>(h3l, rem2, s_w, s_w2, &s_bin, &s_rem, tid, lane, wid);
        unsigned B3 = s_bin, rem3 = s_rem;

        unsigned pref = (B1 << 21) | (B2 << 10);
        {
            unsigned j0 = 2u * tid, j1 = j0 + 1;
            unsigned c0 = s_h2[j0], c1 = s_h2[j1];
            if (j0 > B3 && c0) dsumA += (double)c0 * (double)ordval(pref | j0);
            if (j1 > B3 && c1) dsumB += (double)c1 * (double)ordval(pref | j1);
        }
        float pv = ordval(pref | B3);

        double s = warpRedD(dsumA + dsumB);
        if (lane == 0) sd[wid] = s;
        __syncthreads();
        if (wid == 0) {
            double t = (lane < 16) ? sd[lane] : 0.0;
            t = warpRedD(t);
            if (lane == 0) sd[0] = t + (double)rem3 * (double)pv;
        }
        __syncthreads();
        negsum = sd[0];
    }

    // publish per-batch results; last block combines
    if (tid == 0) {
        double nums = fmax(s_np, (double)EPS16);
        g_ob_cp[b] = s_ce / nums;
        g_ob_cn[b] = negsum / nums;
        g_ob_np[b] = s_np;
        g_ob_sl[b] = s_sl;
        __threadfence();
        s_ticket = atomicAdd(&g_ctr, 1);
    }
    __syncthreads();

    if (s_ticket == NB - 1) {
        double cp = 0.0, cn = 0.0, np = 0.0, sl = 0.0;
        if (tid < NB) {
            cp = g_ob_cp[tid]; cn = g_ob_cn[tid];
            np = g_ob_np[tid]; sl = g_ob_sl[tid];
        }
        cp = warpRedD(cp); cn = warpRedD(cn); np = warpRedD(np); sl = warpRedD(sl);
        __shared__ double f0[2], f1[2], f2[2], f3[2];
        if (lane == 0 && tid < NB) {
            f0[wid] = cp; f1[wid] = cn; f2[wid] = np; f3[wid] = sl;
        }
        __syncthreads();
        if (tid == 0) {
            double CP = f0[0] + f0[1];
            double CN = f1[0] + f1[1];
            double NP = f2[0] + f2[1];
            double SL = f3[0] + f3[1];
            double lbox = SL / fmax(NP, 1.0);
            out[0] = (float)(lbox + CP / (double)NB + CN / (double)NB);
            g_ctr = 0;
        }
    }
}

// ---------------- launch ----------------
extern "C" void kernel_launch(void* const* d_in, const int* in_sizes, int n_in,
                              void* d_out, int out_size) {
    const float* preg = (const float*)d_in[0];
    const float* pcls = (const float*)d_in[1];
    const float* ancs = (const float*)d_in[2];
    const float* gbox = (const float*)d_in[3];
    const int*   glab = (const int*)d_in[4];
    float* out = (float*)d_out;

    dim3 gridm(NBX, NB);
    k_match<<<gridm, 256>>>(preg, pcls, ancs, gbox, glab);
    k_select<<<NB, 512>>>(out);
}